// round 1
// baseline (speedup 1.0000x reference)
#include <cuda_runtime.h>
#include <cuda_bf16.h>

// Problem constants (fixed-shape problem)
#define NB 20000      // nodes
#define BB 64         // batch
#define EE 1280000    // edges

// ---------------- scratch (device globals; no runtime allocation) ----------------
__device__ float g_xt[NB * BB];        // x transposed to [N, B]  (5.12 MB)
__device__ int   g_count[NB];          // histogram of dst
__device__ int   g_row_start[NB + 1];  // CSR offsets
__device__ int   g_cursor[NB];         // mutable copy for scatter
__device__ int   g_ssrc[EE];           // dst-sorted src indices  (5.12 MB)
__device__ float g_sc[EE];             // dst-sorted adj*w        (5.12 MB)

// ---------------- K1: transpose x [B,N] -> xt [N,B], and zero histogram ----------
__global__ __launch_bounds__(256) void k_transpose_zero(const float* __restrict__ x) {
    __shared__ float tile[32][33];
    const int bx = blockIdx.x, by = blockIdx.y;
    const int tx = threadIdx.x, ty = threadIdx.y;   // 32 x 8
    const int n0 = bx * 32, b0 = by * 32;

    #pragma unroll
    for (int i = 0; i < 32; i += 8) {
        int b = b0 + ty + i;
        int n = n0 + tx;                 // N = 20000 = 625*32 exact, B = 64 = 2*32 exact
        tile[ty + i][tx] = x[b * NB + n];
    }
    __syncthreads();
    #pragma unroll
    for (int i = 0; i < 32; i += 8) {
        int n = n0 + ty + i;
        int b = b0 + tx;
        g_xt[n * BB + b] = tile[tx][ty + i];
    }

    // zero histogram using the same grid (runs before the histogram kernel)
    int gid = (by * gridDim.x + bx) * 256 + ty * 32 + tx;
    if (gid < NB) g_count[gid] = 0;
}

// ---------------- K2: histogram of dst --------------------------------------------
__global__ __launch_bounds__(256) void k_hist(const int* __restrict__ dst) {
    int e = blockIdx.x * 256 + threadIdx.x;
    if (e < EE) atomicAdd(&g_count[dst[e]], 1);
}

// ---------------- K3: single-block exclusive scan (20000 elements) ----------------
__global__ __launch_bounds__(1024) void k_scan() {
    __shared__ int warp_sums[32];
    const int t = threadIdx.x;
    const int lane = t & 31, wid = t >> 5;
    const int base = t * 20;             // 1024 * 20 = 20480 >= 20000

    int cnt[20];
    int sum = 0;
    #pragma unroll
    for (int k = 0; k < 20; k++) {
        int idx = base + k;
        cnt[k] = (idx < NB) ? g_count[idx] : 0;
        sum += cnt[k];
    }

    // warp inclusive scan of per-thread sums
    int v = sum;
    #pragma unroll
    for (int o = 1; o < 32; o <<= 1) {
        int u = __shfl_up_sync(0xFFFFFFFFu, v, o);
        if (lane >= o) v += u;
    }
    if (lane == 31) warp_sums[wid] = v;
    __syncthreads();
    if (wid == 0) {
        int w = warp_sums[lane];
        #pragma unroll
        for (int o = 1; o < 32; o <<= 1) {
            int u = __shfl_up_sync(0xFFFFFFFFu, w, o);
            if (lane >= o) w += u;
        }
        warp_sums[lane] = w;             // inclusive warp prefix
    }
    __syncthreads();

    int warp_prefix = (wid > 0) ? warp_sums[wid - 1] : 0;
    int excl = warp_prefix + (v - sum);  // exclusive prefix for this thread
    int run = excl;
    #pragma unroll
    for (int k = 0; k < 20; k++) {
        int idx = base + k;
        if (idx < NB) {
            g_row_start[idx] = run;
            g_cursor[idx]    = run;
            run += cnt[k];
        }
    }
    if (t == 1023) g_row_start[NB] = run;   // = total = EE
}

// ---------------- K4: scatter edges into dst-sorted order -------------------------
__global__ __launch_bounds__(256) void k_scatter(const int* __restrict__ src,
                                                 const int* __restrict__ dst,
                                                 const float* __restrict__ adj,
                                                 const float* __restrict__ w) {
    int e = blockIdx.x * 256 + threadIdx.x;
    if (e < EE) {
        int d = dst[e];
        int pos = atomicAdd(&g_cursor[d], 1);
        g_ssrc[pos] = src[e];
        g_sc[pos]   = adj[e] * w[e];
    }
}

// ---------------- K5: gather-SpMM + fused epilogue --------------------------------
// One warp per dst node. Lane holds float2 accumulator for b = 2*lane, 2*lane+1.
__global__ __launch_bounds__(512) void k_spmm(const float* __restrict__ x,      // for x[0, :]
                                              const float* __restrict__ self_w,
                                              const float* __restrict__ bias,
                                              float* __restrict__ out) {
    const int warp = threadIdx.x >> 5;
    const int lane = threadIdx.x & 31;
    const int n = blockIdx.x * 16 + warp;
    if (n >= NB) return;

    const int start = g_row_start[n];
    const int end   = g_row_start[n + 1];
    const float2* __restrict__ xt2 = reinterpret_cast<const float2*>(g_xt);

    float ax = 0.f, ay = 0.f;

    int i = start;
    for (; i + 4 <= end; i += 4) {
        int   s0 = g_ssrc[i],     s1 = g_ssrc[i + 1];
        int   s2 = g_ssrc[i + 2], s3 = g_ssrc[i + 3];
        float c0 = g_sc[i],       c1 = g_sc[i + 1];
        float c2 = g_sc[i + 2],   c3 = g_sc[i + 3];
        float2 v0 = xt2[s0 * 32 + lane];
        float2 v1 = xt2[s1 * 32 + lane];
        float2 v2 = xt2[s2 * 32 + lane];
        float2 v3 = xt2[s3 * 32 + lane];
        ax += c0 * v0.x; ay += c0 * v0.y;
        ax += c1 * v1.x; ay += c1 * v1.y;
        ax += c2 * v2.x; ay += c2 * v2.y;
        ax += c3 * v3.x; ay += c3 * v3.y;
    }
    for (; i < end; i++) {
        int   s = g_ssrc[i];
        float c = g_sc[i];
        float2 v = xt2[s * 32 + lane];
        ax += c * v.x; ay += c * v.y;
    }

    // epilogue: out[b, n] = relu(acc * x[0,n]*self_w[n] + bias[n])
    const float sl = x[n] * self_w[n];   // x[0*N + n]
    const float bv = bias[n];
    float o0 = fmaxf(ax * sl + bv, 0.0f);
    float o1 = fmaxf(ay * sl + bv, 0.0f);
    out[(2 * lane) * NB + n]     = o0;
    out[(2 * lane + 1) * NB + n] = o1;
}

// ---------------- launch -----------------------------------------------------------
extern "C" void kernel_launch(void* const* d_in, const int* in_sizes, int n_in,
                              void* d_out, int out_size) {
    const float* x      = (const float*)d_in[0];   // [B, N]
    const float* adj    = (const float*)d_in[1];   // [E]
    const float* w      = (const float*)d_in[2];   // [E]
    const float* self_w = (const float*)d_in[3];   // [N]
    const float* bias   = (const float*)d_in[4];   // [N]
    const int*   src    = (const int*)d_in[5];     // [E]
    const int*   dst    = (const int*)d_in[6];     // [E]
    float*       out    = (float*)d_out;           // [B, N]

    dim3 tgrid(NB / 32, BB / 32);                  // 625 x 2
    dim3 tblk(32, 8);
    k_transpose_zero<<<tgrid, tblk>>>(x);

    k_hist<<<EE / 256, 256>>>(dst);

    k_scan<<<1, 1024>>>();

    k_scatter<<<EE / 256, 256>>>(src, dst, adj, w);

    k_spmm<<<(NB + 15) / 16, 512>>>(x, self_w, bias, out);
}

// round 2
// speedup vs baseline: 1.1617x; 1.1617x over previous
#include <cuda_runtime.h>
#include <cuda_bf16.h>

// Problem constants (fixed-shape problem)
#define NB 20000      // nodes
#define BB 64         // batch
#define EE 1280000    // edges

// ---------------- scratch (device globals; no runtime allocation) ----------------
__device__ float     g_xt[NB * BB];        // x transposed to [N, B]  (5.12 MB)
__device__ int       g_count[NB];          // histogram of dst
__device__ int       g_row_start[NB + 1];  // CSR offsets
__device__ int       g_cursor[NB];         // mutable copy for scatter
__device__ long long g_edge[EE];           // packed (coef<<32 | src), dst-sorted (10.24 MB)

__device__ __forceinline__ long long pack_edge(int s, float c) {
    return ((long long)__float_as_int(c) << 32) | (unsigned int)s;
}

// ---------------- K1: transpose x [B,N] -> xt [N,B], and zero histogram ----------
__global__ __launch_bounds__(256) void k_transpose_zero(const float* __restrict__ x) {
    __shared__ float tile[32][33];
    const int bx = blockIdx.x, by = blockIdx.y;
    const int tx = threadIdx.x, ty = threadIdx.y;   // 32 x 8
    const int n0 = bx * 32, b0 = by * 32;

    #pragma unroll
    for (int i = 0; i < 32; i += 8) {
        int b = b0 + ty + i;
        int n = n0 + tx;                 // N = 20000 = 625*32 exact, B = 64 = 2*32 exact
        tile[ty + i][tx] = x[b * NB + n];
    }
    __syncthreads();
    #pragma unroll
    for (int i = 0; i < 32; i += 8) {
        int n = n0 + ty + i;
        int b = b0 + tx;
        g_xt[n * BB + b] = tile[tx][ty + i];
    }

    // zero histogram using the same grid (this kernel runs before k_hist)
    int gid = (by * gridDim.x + bx) * 256 + ty * 32 + tx;
    if (gid < NB) g_count[gid] = 0;
}

// ---------------- K2: histogram of dst (4 edges/thread, int4 loads) ---------------
__global__ __launch_bounds__(256) void k_hist(const int* __restrict__ dst) {
    int t = blockIdx.x * 256 + threadIdx.x;          // EE/4 = 320000 threads exactly
    int4 d4 = reinterpret_cast<const int4*>(dst)[t];
    atomicAdd(&g_count[d4.x], 1);
    atomicAdd(&g_count[d4.y], 1);
    atomicAdd(&g_count[d4.z], 1);
    atomicAdd(&g_count[d4.w], 1);
}

// ---------------- K3: single-block exclusive scan (20000 elements) ----------------
__global__ __launch_bounds__(1024) void k_scan() {
    __shared__ int warp_sums[32];
    const int t = threadIdx.x;
    const int lane = t & 31, wid = t >> 5;
    const int base = t * 20;             // 1024 * 20 = 20480 >= 20000

    int cnt[20];
    int sum = 0;
    #pragma unroll
    for (int k = 0; k < 20; k++) {
        int idx = base + k;
        cnt[k] = (idx < NB) ? g_count[idx] : 0;
        sum += cnt[k];
    }

    // warp inclusive scan of per-thread sums
    int v = sum;
    #pragma unroll
    for (int o = 1; o < 32; o <<= 1) {
        int u = __shfl_up_sync(0xFFFFFFFFu, v, o);
        if (lane >= o) v += u;
    }
    if (lane == 31) warp_sums[wid] = v;
    __syncthreads();
    if (wid == 0) {
        int w = warp_sums[lane];
        #pragma unroll
        for (int o = 1; o < 32; o <<= 1) {
            int u = __shfl_up_sync(0xFFFFFFFFu, w, o);
            if (lane >= o) w += u;
        }
        warp_sums[lane] = w;             // inclusive warp prefix
    }
    __syncthreads();

    int warp_prefix = (wid > 0) ? warp_sums[wid - 1] : 0;
    int excl = warp_prefix + (v - sum);  // exclusive prefix for this thread
    int run = excl;
    #pragma unroll
    for (int k = 0; k < 20; k++) {
        int idx = base + k;
        if (idx < NB) {
            g_row_start[idx] = run;
            g_cursor[idx]    = run;
            run += cnt[k];
        }
    }
    if (t == 1023) g_row_start[NB] = run;   // = total = EE
}

// ---------------- K4: scatter edges into dst-sorted order (4 edges/thread) --------
__global__ __launch_bounds__(256) void k_scatter(const int* __restrict__ src,
                                                 const int* __restrict__ dst,
                                                 const float* __restrict__ adj,
                                                 const float* __restrict__ w) {
    int t = blockIdx.x * 256 + threadIdx.x;          // EE/4 threads exactly
    int4   s4 = reinterpret_cast<const int4*>(src)[t];
    int4   d4 = reinterpret_cast<const int4*>(dst)[t];
    float4 a4 = reinterpret_cast<const float4*>(adj)[t];
    float4 w4 = reinterpret_cast<const float4*>(w)[t];

    // 4 independent atomic->store chains: MLP=4 per thread
    int p0 = atomicAdd(&g_cursor[d4.x], 1);
    int p1 = atomicAdd(&g_cursor[d4.y], 1);
    int p2 = atomicAdd(&g_cursor[d4.z], 1);
    int p3 = atomicAdd(&g_cursor[d4.w], 1);
    g_edge[p0] = pack_edge(s4.x, a4.x * w4.x);
    g_edge[p1] = pack_edge(s4.y, a4.y * w4.y);
    g_edge[p2] = pack_edge(s4.z, a4.z * w4.z);
    g_edge[p3] = pack_edge(s4.w, a4.w * w4.w);
}

// ---------------- K5: gather-SpMM + fused epilogue --------------------------------
// One warp per dst node (16 nodes / block). Lane holds float2 accumulator
// (b = 2*lane, 2*lane+1). Epilogue staged through smem for coalesced out stores.
__global__ __launch_bounds__(512) void k_spmm(const float* __restrict__ x,      // for x[0, :]
                                              const float* __restrict__ self_w,
                                              const float* __restrict__ bias,
                                              float* __restrict__ out) {
    __shared__ float s_out[16][66];      // [node][batch], padded row (64+2)

    const int warp = threadIdx.x >> 5;
    const int lane = threadIdx.x & 31;
    const int n = blockIdx.x * 16 + warp;   // NB = 1250 * 16 exactly, no guard

    const int start = g_row_start[n];
    const int end   = g_row_start[n + 1];
    const float2* __restrict__ xt2 = reinterpret_cast<const float2*>(g_xt);

    float ax = 0.f, ay = 0.f;

    int i = start;
    for (; i + 8 <= end; i += 8) {
        long long p[8];
        #pragma unroll
        for (int k = 0; k < 8; k++) p[k] = g_edge[i + k];
        #pragma unroll
        for (int k = 0; k < 8; k++) {
            int   s = (int)(unsigned int)(p[k] & 0xffffffffll);
            float c = __int_as_float((int)(p[k] >> 32));
            float2 v = xt2[s * 32 + lane];
            ax = fmaf(c, v.x, ax);
            ay = fmaf(c, v.y, ay);
        }
    }
    for (; i < end; i++) {
        long long p = g_edge[i];
        int   s = (int)(unsigned int)(p & 0xffffffffll);
        float c = __int_as_float((int)(p >> 32));
        float2 v = xt2[s * 32 + lane];
        ax = fmaf(c, v.x, ax);
        ay = fmaf(c, v.y, ay);
    }

    // epilogue math: out[b, n] = relu(acc * x[0,n]*self_w[n] + bias[n])
    const float sl = x[n] * self_w[n];   // x[0*N + n]
    const float bv = bias[n];
    float o0 = fmaxf(ax * sl + bv, 0.0f);
    float o1 = fmaxf(ay * sl + bv, 0.0f);

    // stage [node][batch] in smem, then write coalesced 64B runs per out row
    s_out[warp][2 * lane]     = o0;
    s_out[warp][2 * lane + 1] = o1;
    __syncthreads();

    const int n0 = blockIdx.x * 16;
    const int j  = threadIdx.x & 15;     // node within block
    int b = threadIdx.x >> 4;            // 0..31, then +32
    out[b * NB + n0 + j]        = s_out[j][b];
    out[(b + 32) * NB + n0 + j] = s_out[j][b + 32];
}

// ---------------- launch -----------------------------------------------------------
extern "C" void kernel_launch(void* const* d_in, const int* in_sizes, int n_in,
                              void* d_out, int out_size) {
    const float* x      = (const float*)d_in[0];   // [B, N]
    const float* adj    = (const float*)d_in[1];   // [E]
    const float* w      = (const float*)d_in[2];   // [E]
    const float* self_w = (const float*)d_in[3];   // [N]
    const float* bias   = (const float*)d_in[4];   // [N]
    const int*   src    = (const int*)d_in[5];     // [E]
    const int*   dst    = (const int*)d_in[6];     // [E]
    float*       out    = (float*)d_out;           // [B, N]

    dim3 tgrid(NB / 32, BB / 32);                  // 625 x 2
    dim3 tblk(32, 8);
    k_transpose_zero<<<tgrid, tblk>>>(x);

    k_hist<<<EE / 1024, 256>>>(dst);               // 1250 blocks, 4 edges/thread

    k_scan<<<1, 1024>>>();

    k_scatter<<<EE / 1024, 256>>>(src, dst, adj, w);

    k_spmm<<<NB / 16, 512>>>(x, self_w, bias, out);
}

// round 3
// speedup vs baseline: 1.1625x; 1.0007x over previous
#include <cuda_runtime.h>
#include <cuda_bf16.h>

// Problem constants (fixed-shape problem)
#define NB 20000      // nodes
#define BB 64         // batch
#define EE 1280000    // edges
#define PAD 32        // counters padded to one 128B line each

// ---------------- scratch (device globals; no runtime allocation) ----------------
__device__ float     g_xt[NB * BB];          // x transposed to [N, B]  (5.12 MB)
__device__ int       g_countP[NB * PAD];     // padded histogram (2.56 MB); ZERO invariant at launch entry
__device__ int       g_row_start[NB + 1];    // CSR offsets
__device__ int       g_cursorP[NB * PAD];    // padded cursors  (2.56 MB)
__device__ long long g_edge[EE];             // packed (coef<<32 | src), dst-sorted (10.24 MB)

__device__ __forceinline__ long long pack_edge(int s, float c) {
    return ((long long)__float_as_int(c) << 32) | (unsigned int)s;
}

// ---------------- K1: transpose x [B,N] -> xt [N,B]  +  histogram of dst ----------
// grid = (625, 2) x (32, 8) = 1250 blocks * 256 threads = 320000 = EE/4
__global__ __launch_bounds__(256) void k_pre(const float* __restrict__ x,
                                             const int* __restrict__ dst) {
    __shared__ float tile[32][33];
    const int bx = blockIdx.x, by = blockIdx.y;
    const int tx = threadIdx.x, ty = threadIdx.y;   // 32 x 8
    const int n0 = bx * 32, b0 = by * 32;

    // histogram part first (independent; memory ops overlap the transpose)
    {
        int t = (by * gridDim.x + bx) * 256 + ty * 32 + tx;   // [0, EE/4)
        int4 d4 = reinterpret_cast<const int4*>(dst)[t];
        atomicAdd(&g_countP[d4.x * PAD], 1);
        atomicAdd(&g_countP[d4.y * PAD], 1);
        atomicAdd(&g_countP[d4.z * PAD], 1);
        atomicAdd(&g_countP[d4.w * PAD], 1);
    }

    #pragma unroll
    for (int i = 0; i < 32; i += 8) {
        int b = b0 + ty + i;
        int n = n0 + tx;                 // N = 625*32 exact, B = 2*32 exact
        tile[ty + i][tx] = x[b * NB + n];
    }
    __syncthreads();
    #pragma unroll
    for (int i = 0; i < 32; i += 8) {
        int n = n0 + ty + i;
        int b = b0 + tx;
        g_xt[n * BB + b] = tile[tx][ty + i];
    }
}

// ---------------- K2: single-block exclusive scan (20000 elements) ----------------
__global__ __launch_bounds__(1024) void k_scan() {
    __shared__ int warp_sums[32];
    const int t = threadIdx.x;
    const int lane = t & 31, wid = t >> 5;
    const int base = t * 20;             // 1024 * 20 = 20480 >= 20000

    int cnt[20];
    int sum = 0;
    #pragma unroll
    for (int k = 0; k < 20; k++) {
        int idx = base + k;
        cnt[k] = (idx < NB) ? g_countP[idx * PAD] : 0;
        sum += cnt[k];
    }

    int v = sum;
    #pragma unroll
    for (int o = 1; o < 32; o <<= 1) {
        int u = __shfl_up_sync(0xFFFFFFFFu, v, o);
        if (lane >= o) v += u;
    }
    if (lane == 31) warp_sums[wid] = v;
    __syncthreads();
    if (wid == 0) {
        int w = warp_sums[lane];
        #pragma unroll
        for (int o = 1; o < 32; o <<= 1) {
            int u = __shfl_up_sync(0xFFFFFFFFu, w, o);
            if (lane >= o) w += u;
        }
        warp_sums[lane] = w;
    }
    __syncthreads();

    int warp_prefix = (wid > 0) ? warp_sums[wid - 1] : 0;
    int excl = warp_prefix + (v - sum);
    int run = excl;
    #pragma unroll
    for (int k = 0; k < 20; k++) {
        int idx = base + k;
        if (idx < NB) {
            g_row_start[idx]      = run;
            g_cursorP[idx * PAD]  = run;
            run += cnt[k];
        }
    }
    if (t == 1023) g_row_start[NB] = run;   // = EE
}

// ---------------- K3: scatter edges into dst-sorted order (8 edges/thread) --------
// Also re-zeroes g_countP (scan has consumed it) to restore the launch invariant.
__global__ __launch_bounds__(256) void k_scatter(const int* __restrict__ src,
                                                 const int* __restrict__ dst,
                                                 const float* __restrict__ adj,
                                                 const float* __restrict__ w) {
    int t = blockIdx.x * 256 + threadIdx.x;          // 625 blocks -> EE/8 = 160000 threads

    const int4*   src4 = reinterpret_cast<const int4*>(src);
    const int4*   dst4 = reinterpret_cast<const int4*>(dst);
    const float4* adj4 = reinterpret_cast<const float4*>(adj);
    const float4* w4p  = reinterpret_cast<const float4*>(w);

    int4   sA = src4[2 * t],     sB = src4[2 * t + 1];
    int4   dA = dst4[2 * t],     dB = dst4[2 * t + 1];
    float4 aA = adj4[2 * t],     aB = adj4[2 * t + 1];
    float4 wA = w4p[2 * t],      wB = w4p[2 * t + 1];

    // restore zero invariant for next launch (count already consumed by k_scan)
    if (t < NB) g_countP[t * PAD] = 0;

    int p0 = atomicAdd(&g_cursorP[dA.x * PAD], 1);
    int p1 = atomicAdd(&g_cursorP[dA.y * PAD], 1);
    int p2 = atomicAdd(&g_cursorP[dA.z * PAD], 1);
    int p3 = atomicAdd(&g_cursorP[dA.w * PAD], 1);
    int p4 = atomicAdd(&g_cursorP[dB.x * PAD], 1);
    int p5 = atomicAdd(&g_cursorP[dB.y * PAD], 1);
    int p6 = atomicAdd(&g_cursorP[dB.z * PAD], 1);
    int p7 = atomicAdd(&g_cursorP[dB.w * PAD], 1);

    g_edge[p0] = pack_edge(sA.x, aA.x * wA.x);
    g_edge[p1] = pack_edge(sA.y, aA.y * wA.y);
    g_edge[p2] = pack_edge(sA.z, aA.z * wA.z);
    g_edge[p3] = pack_edge(sA.w, aA.w * wA.w);
    g_edge[p4] = pack_edge(sB.x, aB.x * wB.x);
    g_edge[p5] = pack_edge(sB.y, aB.y * wB.y);
    g_edge[p6] = pack_edge(sB.z, aB.z * wB.z);
    g_edge[p7] = pack_edge(sB.w, aB.w * wB.w);
}

// ---------------- K4: gather-SpMM + fused epilogue --------------------------------
// 8 nodes per block, 2 warps per node (edge list split in half).
// Lane holds float2 accumulator (b = 2*lane, 2*lane+1).
// Edge payloads staged through smem (coalesced load, broadcast reads).
__global__ __launch_bounds__(512) void k_spmm(const float* __restrict__ x,      // for x[0, :]
                                              const float* __restrict__ self_w,
                                              const float* __restrict__ bias,
                                              float* __restrict__ out) {
    __shared__ long long s_pay[16][33];   // 32 payloads per warp (+pad)
    __shared__ float2    s_red[8][32];    // partial from odd warp
    __shared__ float     s_out[8][65];    // [node][batch] staged output

    const int warp = threadIdx.x >> 5;
    const int lane = threadIdx.x & 31;
    const int node = warp >> 1;           // 0..7
    const int half = warp & 1;
    const int n = blockIdx.x * 8 + node;  // NB = 2500 * 8 exact

    const int start = g_row_start[n];
    const int end   = g_row_start[n + 1];
    const int mid   = (start + end) >> 1;
    const int lo    = half ? mid : start;
    const int hi    = half ? end : mid;

    const float2* __restrict__ xt2 = reinterpret_cast<const float2*>(g_xt);

    float ax = 0.f, ay = 0.f;

    for (int base = lo; base < hi; base += 32) {
        const int cnt = min(32, hi - base);
        if (lane < cnt) s_pay[warp][lane] = g_edge[base + lane];
        __syncwarp();

        int k = 0;
        for (; k + 8 <= cnt; k += 8) {
            #pragma unroll
            for (int u = 0; u < 8; u++) {
                long long p = s_pay[warp][k + u];
                int   s = (int)(unsigned int)(p & 0xffffffffll);
                float c = __int_as_float((int)(p >> 32));
                float2 v = xt2[s * 32 + lane];
                ax = fmaf(c, v.x, ax);
                ay = fmaf(c, v.y, ay);
            }
        }
        for (; k < cnt; k++) {
            long long p = s_pay[warp][k];
            int   s = (int)(unsigned int)(p & 0xffffffffll);
            float c = __int_as_float((int)(p >> 32));
            float2 v = xt2[s * 32 + lane];
            ax = fmaf(c, v.x, ax);
            ay = fmaf(c, v.y, ay);
        }
        __syncwarp();
    }

    if (half == 1) s_red[node][lane] = make_float2(ax, ay);
    __syncthreads();

    if (half == 0) {
        float2 r = s_red[node][lane];
        ax += r.x;  ay += r.y;
        const float sl = x[n] * self_w[n];   // x[0*N + n]
        const float bv = bias[n];
        s_out[node][2 * lane]     = fmaxf(ax * sl + bv, 0.0f);
        s_out[node][2 * lane + 1] = fmaxf(ay * sl + bv, 0.0f);
    }
    __syncthreads();

    // coalesced output: 512 threads = 8 nodes x 64 batch
    const int j = threadIdx.x & 7;        // node within block
    const int b = threadIdx.x >> 3;       // batch
    out[b * NB + blockIdx.x * 8 + j] = s_out[j][b];
}

// ---------------- launch -----------------------------------------------------------
extern "C" void kernel_launch(void* const* d_in, const int* in_sizes, int n_in,
                              void* d_out, int out_size) {
    const float* x      = (const float*)d_in[0];   // [B, N]
    const float* adj    = (const float*)d_in[1];   // [E]
    const float* w      = (const float*)d_in[2];   // [E]
    const float* self_w = (const float*)d_in[3];   // [N]
    const float* bias   = (const float*)d_in[4];   // [N]
    const int*   src    = (const int*)d_in[5];     // [E]
    const int*   dst    = (const int*)d_in[6];     // [E]
    float*       out    = (float*)d_out;           // [B, N]

    dim3 tgrid(NB / 32, BB / 32);                  // 625 x 2 = 1250 blocks
    dim3 tblk(32, 8);
    k_pre<<<tgrid, tblk>>>(x, dst);                // transpose + histogram

    k_scan<<<1, 1024>>>();

    k_scatter<<<EE / 2048, 256>>>(src, dst, adj, w);  // 625 blocks, 8 edges/thread

    k_spmm<<<NB / 8, 512>>>(x, self_w, bias, out);
}

// round 4
// speedup vs baseline: 1.3105x; 1.1273x over previous
#include <cuda_runtime.h>
#include <cuda_bf16.h>

// Problem constants (fixed-shape problem)
#define NB 20000      // nodes
#define BB 64         // batch
#define EE 1280000    // edges

// ---------------- scratch (device globals; no runtime allocation) ----------------
__device__ float     g_xt[NB * BB];        // x transposed to [N, B]  (5.12 MB)
__device__ int       g_count[NB];          // histogram of dst; ZERO invariant at launch entry
__device__ int       g_rank[EE];           // per-edge rank within its dst bucket (5.12 MB)
__device__ int       g_row_start[NB + 1];  // CSR offsets
__device__ long long g_edge[EE];           // packed (coef<<32 | src), dst-sorted (10.24 MB)

__device__ __forceinline__ long long pack_edge(int s, float c) {
    return ((long long)__float_as_int(c) << 32) | (unsigned int)s;
}

// ---------------- K1: transpose x [B,N] -> xt [N,B]  +  rank-histogram of dst -----
// grid = (625, 2) x (32, 8) = 1250 blocks * 256 threads = 320000 = EE/4
__global__ __launch_bounds__(256) void k_pre(const float* __restrict__ x,
                                             const int* __restrict__ dst) {
    __shared__ float tile[32][33];
    const int bx = blockIdx.x, by = blockIdx.y;
    const int tx = threadIdx.x, ty = threadIdx.y;   // 32 x 8
    const int n0 = bx * 32, b0 = by * 32;

    // rank-histogram: rank[e] = atomicAdd(count[dst[e]], 1)  (overlaps the transpose)
    {
        int t = (by * gridDim.x + bx) * 256 + ty * 32 + tx;   // [0, EE/4)
        int4 d4 = reinterpret_cast<const int4*>(dst)[t];
        int4 r4;
        r4.x = atomicAdd(&g_count[d4.x], 1);
        r4.y = atomicAdd(&g_count[d4.y], 1);
        r4.z = atomicAdd(&g_count[d4.z], 1);
        r4.w = atomicAdd(&g_count[d4.w], 1);
        reinterpret_cast<int4*>(g_rank)[t] = r4;
    }

    #pragma unroll
    for (int i = 0; i < 32; i += 8) {
        int b = b0 + ty + i;
        int n = n0 + tx;                 // N = 625*32 exact, B = 2*32 exact
        tile[ty + i][tx] = x[b * NB + n];
    }
    __syncthreads();
    #pragma unroll
    for (int i = 0; i < 32; i += 8) {
        int n = n0 + ty + i;
        int b = b0 + tx;
        g_xt[n * BB + b] = tile[tx][ty + i];
    }
}

// ---------------- K2: single-block exclusive scan (20000 elements) ----------------
__global__ __launch_bounds__(1024) void k_scan() {
    __shared__ int warp_sums[32];
    const int t = threadIdx.x;
    const int lane = t & 31, wid = t >> 5;
    const int base = t * 20;             // 1024 * 20 = 20480 >= 20000

    int cnt[20];
    int sum = 0;
    #pragma unroll
    for (int k = 0; k < 20; k++) {
        int idx = base + k;
        cnt[k] = (idx < NB) ? g_count[idx] : 0;
        sum += cnt[k];
    }

    int v = sum;
    #pragma unroll
    for (int o = 1; o < 32; o <<= 1) {
        int u = __shfl_up_sync(0xFFFFFFFFu, v, o);
        if (lane >= o) v += u;
    }
    if (lane == 31) warp_sums[wid] = v;
    __syncthreads();
    if (wid == 0) {
        int w = warp_sums[lane];
        #pragma unroll
        for (int o = 1; o < 32; o <<= 1) {
            int u = __shfl_up_sync(0xFFFFFFFFu, w, o);
            if (lane >= o) w += u;
        }
        warp_sums[lane] = w;
    }
    __syncthreads();

    int warp_prefix = (wid > 0) ? warp_sums[wid - 1] : 0;
    int excl = warp_prefix + (v - sum);
    int run = excl;
    #pragma unroll
    for (int k = 0; k < 20; k++) {
        int idx = base + k;
        if (idx < NB) {
            g_row_start[idx] = run;
            run += cnt[k];
        }
    }
    if (t == 1023) g_row_start[NB] = run;   // = EE
}

// ---------------- K3: atomic-free scatter (8 edges/thread) ------------------------
// pos = row_start[dst] + rank.  Also re-zeroes g_count (restores launch invariant).
__global__ __launch_bounds__(256) void k_scatter(const int* __restrict__ src,
                                                 const int* __restrict__ dst,
                                                 const float* __restrict__ adj,
                                                 const float* __restrict__ w) {
    int t = blockIdx.x * 256 + threadIdx.x;          // 625 blocks -> EE/8 = 160000 threads

    const int4*   src4 = reinterpret_cast<const int4*>(src);
    const int4*   dst4 = reinterpret_cast<const int4*>(dst);
    const float4* adj4 = reinterpret_cast<const float4*>(adj);
    const float4* w4p  = reinterpret_cast<const float4*>(w);
    const int4*   rnk4 = reinterpret_cast<const int4*>(g_rank);

    int4   sA = src4[2 * t],  sB = src4[2 * t + 1];
    int4   dA = dst4[2 * t],  dB = dst4[2 * t + 1];
    float4 aA = adj4[2 * t],  aB = adj4[2 * t + 1];
    float4 wA = w4p[2 * t],   wB = w4p[2 * t + 1];
    int4   rA = rnk4[2 * t],  rB = rnk4[2 * t + 1];

    // restore zero invariant for next launch (count consumed by k_scan)
    if (t < NB) g_count[t] = 0;

    int p0 = g_row_start[dA.x] + rA.x;
    int p1 = g_row_start[dA.y] + rA.y;
    int p2 = g_row_start[dA.z] + rA.z;
    int p3 = g_row_start[dA.w] + rA.w;
    int p4 = g_row_start[dB.x] + rB.x;
    int p5 = g_row_start[dB.y] + rB.y;
    int p6 = g_row_start[dB.z] + rB.z;
    int p7 = g_row_start[dB.w] + rB.w;

    g_edge[p0] = pack_edge(sA.x, aA.x * wA.x);
    g_edge[p1] = pack_edge(sA.y, aA.y * wA.y);
    g_edge[p2] = pack_edge(sA.z, aA.z * wA.z);
    g_edge[p3] = pack_edge(sA.w, aA.w * wA.w);
    g_edge[p4] = pack_edge(sB.x, aB.x * wB.x);
    g_edge[p5] = pack_edge(sB.y, aB.y * wB.y);
    g_edge[p6] = pack_edge(sB.z, aB.z * wB.z);
    g_edge[p7] = pack_edge(sB.w, aB.w * wB.w);
}

// ---------------- K4: gather-SpMM + fused epilogue --------------------------------
// 8 nodes per block, 2 warps per node (edge list split in half).
// Lane holds packed float2 accumulators (b = 2*lane, 2*lane+1); FFMA2, 2 chains.
__global__ __launch_bounds__(512) void k_spmm(const float* __restrict__ x,      // for x[0, :]
                                              const float* __restrict__ self_w,
                                              const float* __restrict__ bias,
                                              float* __restrict__ out) {
    __shared__ long long s_pay[16][33];   // 32 payloads per warp (+pad)
    __shared__ float2    s_red[8][32];    // partial from odd warp
    __shared__ float     s_out[8][65];    // [node][batch] staged output

    const int warp = threadIdx.x >> 5;
    const int lane = threadIdx.x & 31;
    const int node = warp >> 1;           // 0..7
    const int half = warp & 1;
    const int n = blockIdx.x * 8 + node;  // NB = 2500 * 8 exact

    const int start = g_row_start[n];
    const int end   = g_row_start[n + 1];
    const int mid   = (start + end) >> 1;
    const int lo    = half ? mid : start;
    const int hi    = half ? end : mid;

    const float2* __restrict__ xt2 = reinterpret_cast<const float2*>(g_xt);

    unsigned long long acc0 = 0ull, acc1 = 0ull;   // packed {f32,f32} accumulators

    for (int base = lo; base < hi; base += 32) {
        const int cnt = min(32, hi - base);
        if (lane < cnt) s_pay[warp][lane] = g_edge[base + lane];
        __syncwarp();

        int k = 0;
        for (; k + 8 <= cnt; k += 8) {
            #pragma unroll
            for (int u = 0; u < 8; u++) {
                long long p = s_pay[warp][k + u];
                int s  = (int)(unsigned int)(p & 0xffffffffll);
                int cb = (int)(p >> 32);
                unsigned long long cc, v64;
                asm("mov.b64 %0, {%1, %1};" : "=l"(cc) : "r"(cb));
                float2 v = xt2[s * 32 + lane];
                v64 = *reinterpret_cast<unsigned long long*>(&v);
                if (u & 1) asm("fma.rn.f32x2 %0, %1, %2, %0;" : "+l"(acc1) : "l"(v64), "l"(cc));
                else       asm("fma.rn.f32x2 %0, %1, %2, %0;" : "+l"(acc0) : "l"(v64), "l"(cc));
            }
        }
        for (; k < cnt; k++) {
            long long p = s_pay[warp][k];
            int s  = (int)(unsigned int)(p & 0xffffffffll);
            int cb = (int)(p >> 32);
            unsigned long long cc, v64;
            asm("mov.b64 %0, {%1, %1};" : "=l"(cc) : "r"(cb));
            float2 v = xt2[s * 32 + lane];
            v64 = *reinterpret_cast<unsigned long long*>(&v);
            if (k & 1) asm("fma.rn.f32x2 %0, %1, %2, %0;" : "+l"(acc1) : "l"(v64), "l"(cc));
            else       asm("fma.rn.f32x2 %0, %1, %2, %0;" : "+l"(acc0) : "l"(v64), "l"(cc));
        }
        __syncwarp();
    }

    // combine the two packed chains
    unsigned long long accT;
    asm("add.rn.f32x2 %0, %1, %2;" : "=l"(accT) : "l"(acc0), "l"(acc1));
    float2 a = *reinterpret_cast<float2*>(&accT);

    if (half == 1) s_red[node][lane] = a;
    __syncthreads();

    if (half == 0) {
        float2 r = s_red[node][lane];
        float ax = a.x + r.x;
        float ay = a.y + r.y;
        const float sl = x[n] * self_w[n];   // x[0*N + n]
        const float bv = bias[n];
        s_out[node][2 * lane]     = fmaxf(ax * sl + bv, 0.0f);
        s_out[node][2 * lane + 1] = fmaxf(ay * sl + bv, 0.0f);
    }
    __syncthreads();

    // coalesced output: 512 threads = 8 nodes x 64 batch
    const int j = threadIdx.x & 7;        // node within block
    const int b = threadIdx.x >> 3;       // batch
    out[b * NB + blockIdx.x * 8 + j] = s_out[j][b];
}

// ---------------- launch -----------------------------------------------------------
extern "C" void kernel_launch(void* const* d_in, const int* in_sizes, int n_in,
                              void* d_out, int out_size) {
    const float* x      = (const float*)d_in[0];   // [B, N]
    const float* adj    = (const float*)d_in[1];   // [E]
    const float* w      = (const float*)d_in[2];   // [E]
    const float* self_w = (const float*)d_in[3];   // [N]
    const float* bias   = (const float*)d_in[4];   // [N]
    const int*   src    = (const int*)d_in[5];     // [E]
    const int*   dst    = (const int*)d_in[6];     // [E]
    float*       out    = (float*)d_out;           // [B, N]

    dim3 tgrid(NB / 32, BB / 32);                  // 625 x 2 = 1250 blocks
    dim3 tblk(32, 8);
    k_pre<<<tgrid, tblk>>>(x, dst);                // transpose + rank-histogram

    k_scan<<<1, 1024>>>();

    k_scatter<<<EE / 2048, 256>>>(src, dst, adj, w);  // atomic-free permute

    k_spmm<<<NB / 8, 512>>>(x, self_w, bias, out);
}